// round 7
// baseline (speedup 1.0000x reference)
#include <cuda_runtime.h>
#include <math.h>

// ---------------- problem constants ----------------
#define BATCH   64
#define NC      1024
#define NT      1024
#define PTS     (BATCH * (NC + NT))   // 131072, rows 0..65535 = context, 65536.. = target
#define HID     512
#define FW      576                   // padded feature width (513 -> 576 = 9*64)
#define NP      576
#define NB      64
#define NBLK    9

typedef unsigned long long ull;

// ---------------- scratch (device globals; no allocation allowed) ----------------
__device__ float  g_buf0[(size_t)PTS * HID];
__device__ float  g_buf1[(size_t)PTS * HID];
__device__ float  g_bufR[(size_t)PTS * FW];
__device__ float  g_cov[(size_t)BATCH * NP * NP];
__device__ float  g_xty[BATCH * NP];
__device__ float  g_w[BATCH * NP];
__device__ float2 g_stats[BATCH];     // (mean, std)

// ---------------- f32x2 helpers (Blackwell packed fp32) ----------------
__device__ __forceinline__ ull pack2(float lo, float hi) {
    ull r; asm("mov.b64 %0, {%1, %2};" : "=l"(r) : "f"(lo), "f"(hi)); return r;
}
__device__ __forceinline__ void unpack2(ull v, float& lo, float& hi) {
    asm("mov.b64 {%0, %1}, %2;" : "=f"(lo), "=f"(hi) : "l"(v));
}
__device__ __forceinline__ ull ffma2(ull a, ull b, ull c) {
    ull d; asm("fma.rn.f32x2 %0, %1, %2, %3;" : "=l"(d) : "l"(a), "l"(b), "l"(c));
    return d;
}
__device__ __forceinline__ float warpsum(float v) {
    #pragma unroll
    for (int o = 16; o; o >>= 1) v += __shfl_xor_sync(0xffffffffu, v, o);
    return v;
}

// ---------------- y-context stats (mean, std ddof=1) ----------------
__global__ void stats_kernel(const float* __restrict__ y) {
    int b = blockIdx.x, tid = threadIdx.x;
    double s = 0.0, ss = 0.0;
    for (int n = tid; n < NC; n += 256) {
        double v = (double)y[b * NC + n];
        s += v; ss += v * v;
    }
    #pragma unroll
    for (int o = 16; o; o >>= 1) {
        s  += __shfl_xor_sync(0xffffffffu, s,  o);
        ss += __shfl_xor_sync(0xffffffffu, ss, o);
    }
    __shared__ double sh0[8], sh1[8];
    int w = tid >> 5, l = tid & 31;
    if (l == 0) { sh0[w] = s; sh1[w] = ss; }
    __syncthreads();
    if (tid == 0) {
        double S = 0.0, SS = 0.0;
        for (int i = 0; i < 8; i++) { S += sh0[i]; SS += sh1[i]; }
        double mean = S / (double)NC;
        double var  = (SS - (double)NC * mean * mean) / (double)(NC - 1);
        g_stats[b] = make_float2((float)mean, (float)sqrt(var));
    }
}

// ---------------- SIREN layer 0 (XD = 1) ----------------
__global__ void layer0_kernel(const float* __restrict__ xc, const float* __restrict__ xt,
                              const float* __restrict__ W0, const float* __restrict__ b0) {
    int p = blockIdx.x;
    float x = (p < BATCH * NC) ? xc[p] : xt[p - BATCH * NC];
    int j = threadIdx.x * 4;
    float4 w = *(const float4*)&W0[j];
    float4 bb = *(const float4*)&b0[j];
    float4 o;
    o.x = sinf(30.0f * fmaf(x, w.x, bb.x));
    o.y = sinf(30.0f * fmaf(x, w.y, bb.y));
    o.z = sinf(30.0f * fmaf(x, w.z, bb.z));
    o.w = sinf(30.0f * fmaf(x, w.w, bb.w));
    *(float4*)&g_buf0[(size_t)p * HID + j] = o;
}

// ---------------- main fp32 GEMM: C[M x 512] = act(A[M x 512] @ W + bias) ----------------
#define BM 128
#define BN 128
#define BK 16

__global__ __launch_bounds__(256, 2)
void gemm_kernel(int aSel, const float* __restrict__ W, const float* __restrict__ bias,
                 int cSel, int ldc, int applySin) {
    const float* A = (aSel == 0) ? g_buf0 : g_buf1;
    float* C = (cSel == 0) ? g_buf0 : (cSel == 1 ? g_buf1 : g_bufR);

    __shared__ __align__(16) float As[2][BK][BM];
    __shared__ __align__(16) float Bs[2][BK][BN];

    const int tid = threadIdx.x;
    const int m0 = blockIdx.x * BM;
    const int n0 = blockIdx.y * BN;

    const int arow = tid & 127;
    const int acol = (tid >> 7) * 8;      // 0 or 8
    const int brow = tid >> 4;            // 0..15
    const int bcol = (tid & 15) * 8;

    const float* Ag = A + (size_t)(m0 + arow) * HID + acol;
    const float* Bg = W + (size_t)brow * HID + n0 + bcol;

    float4 ar0 = *(const float4*)(Ag + 0);
    float4 ar1 = *(const float4*)(Ag + 4);
    float4 br0 = *(const float4*)(Bg + 0);
    float4 br1 = *(const float4*)(Bg + 4);

    As[0][acol + 0][arow] = ar0.x; As[0][acol + 1][arow] = ar0.y;
    As[0][acol + 2][arow] = ar0.z; As[0][acol + 3][arow] = ar0.w;
    As[0][acol + 4][arow] = ar1.x; As[0][acol + 5][arow] = ar1.y;
    As[0][acol + 6][arow] = ar1.z; As[0][acol + 7][arow] = ar1.w;
    *(float4*)&Bs[0][brow][bcol]     = br0;
    *(float4*)&Bs[0][brow][bcol + 4] = br1;
    __syncthreads();

    const int ty = tid >> 4, tx = tid & 15;
    ull acc[8][4];
    #pragma unroll
    for (int i = 0; i < 8; i++)
        #pragma unroll
        for (int j = 0; j < 4; j++) acc[i][j] = 0ull;

    const int nTiles = HID / BK;   // 32
    int buf = 0;
    for (int t = 0; t < nTiles; ++t) {
        if (t + 1 < nTiles) {
            const float* Ag2 = Ag + (t + 1) * BK;
            const float* Bg2 = Bg + (size_t)(t + 1) * BK * HID;
            ar0 = *(const float4*)(Ag2 + 0);
            ar1 = *(const float4*)(Ag2 + 4);
            br0 = *(const float4*)(Bg2 + 0);
            br1 = *(const float4*)(Bg2 + 4);
        }
        #pragma unroll
        for (int kk = 0; kk < BK; ++kk) {
            float4 av0 = *(const float4*)&As[buf][kk][ty * 8];
            float4 av1 = *(const float4*)&As[buf][kk][ty * 8 + 4];
            ulonglong2 bv0 = *(const ulonglong2*)&Bs[buf][kk][tx * 8];
            ulonglong2 bv1 = *(const ulonglong2*)&Bs[buf][kk][tx * 8 + 4];
            ull bb[4] = { bv0.x, bv0.y, bv1.x, bv1.y };
            float a_[8] = { av0.x, av0.y, av0.z, av0.w, av1.x, av1.y, av1.z, av1.w };
            #pragma unroll
            for (int i = 0; i < 8; i++) {
                ull ad = pack2(a_[i], a_[i]);
                #pragma unroll
                for (int j = 0; j < 4; j++) acc[i][j] = ffma2(ad, bb[j], acc[i][j]);
            }
        }
        if (t + 1 < nTiles) {
            __syncthreads();
            int nb = buf ^ 1;
            As[nb][acol + 0][arow] = ar0.x; As[nb][acol + 1][arow] = ar0.y;
            As[nb][acol + 2][arow] = ar0.z; As[nb][acol + 3][arow] = ar0.w;
            As[nb][acol + 4][arow] = ar1.x; As[nb][acol + 5][arow] = ar1.y;
            As[nb][acol + 6][arow] = ar1.z; As[nb][acol + 7][arow] = ar1.w;
            *(float4*)&Bs[nb][brow][bcol]     = br0;
            *(float4*)&Bs[nb][brow][bcol + 4] = br1;
            __syncthreads();
            buf = nb;
        }
    }

    #pragma unroll
    for (int i = 0; i < 8; i++) {
        int m = m0 + ty * 8 + i;
        float* Crow = C + (size_t)m * ldc + n0 + tx * 8;
        #pragma unroll
        for (int j = 0; j < 4; j++) {
            float lo, hi; unpack2(acc[i][j], lo, hi);
            int col = n0 + tx * 8 + 2 * j;
            lo += bias[col]; hi += bias[col + 1];
            if (applySin) { lo = sinf(lo); hi = sinf(hi); }
            *(float2*)&Crow[2 * j] = make_float2(lo, hi);
        }
    }
}

// ---------------- pad feature cols: col 512 = 1, cols 513..575 = 0 ----------------
__global__ void padfill_kernel() {
    size_t p = blockIdx.x;
    int t = threadIdx.x;     // 64
    g_bufR[p * FW + HID + t] = (t == 0) ? 1.0f : 0.0f;
}

// ---------------- batched SYRK: cov[b] = F_b^T F_b (lower tiles only) ----------------
__global__ __launch_bounds__(256)
void syrk_kernel() {
    int bx = blockIdx.x;
    int batch = bx / 45;
    int p = bx % 45;
    int ti = 0;
    while ((ti + 1) * (ti + 2) / 2 <= p) ti++;
    int tj = p - ti * (ti + 1) / 2;

    const float* F = g_bufR + (size_t)batch * NC * FW;
    __shared__ __align__(16) float Sa[2][16][64];
    __shared__ __align__(16) float Sb[2][16][64];

    int tid = threadIdx.x;
    int lr = tid >> 4;            // 0..15 (K row)
    int lc = (tid & 15) * 4;      // col within tile
    const float* Fa = F + (size_t)lr * FW + ti * 64 + lc;
    const float* Fb = F + (size_t)lr * FW + tj * 64 + lc;

    float4 ra = *(const float4*)Fa;
    float4 rb = *(const float4*)Fb;
    *(float4*)&Sa[0][lr][lc] = ra;
    *(float4*)&Sb[0][lr][lc] = rb;
    __syncthreads();

    ull acc[4][2];
    #pragma unroll
    for (int i = 0; i < 4; i++) { acc[i][0] = 0ull; acc[i][1] = 0ull; }

    int ty = tid >> 4, tx = tid & 15;
    int buf = 0;
    for (int t = 0; t < 64; ++t) {     // K = 1024 / 16
        if (t + 1 < 64) {
            ra = *(const float4*)(Fa + (size_t)(t + 1) * 16 * FW);
            rb = *(const float4*)(Fb + (size_t)(t + 1) * 16 * FW);
        }
        #pragma unroll
        for (int kk = 0; kk < 16; ++kk) {
            float4 av = *(const float4*)&Sa[buf][kk][ty * 4];
            ulonglong2 bv = *(const ulonglong2*)&Sb[buf][kk][tx * 4];
            ull bb[2] = { bv.x, bv.y };
            float a_[4] = { av.x, av.y, av.z, av.w };
            #pragma unroll
            for (int i = 0; i < 4; i++) {
                ull ad = pack2(a_[i], a_[i]);
                acc[i][0] = ffma2(ad, bb[0], acc[i][0]);
                acc[i][1] = ffma2(ad, bb[1], acc[i][1]);
            }
        }
        if (t + 1 < 64) {
            __syncthreads();
            int nb = buf ^ 1;
            *(float4*)&Sa[nb][lr][lc] = ra;
            *(float4*)&Sb[nb][lr][lc] = rb;
            __syncthreads();
            buf = nb;
        }
    }

    float* Cb = g_cov + (size_t)batch * NP * NP;
    #pragma unroll
    for (int i = 0; i < 4; i++) {
        int ii = ti * 64 + ty * 4 + i;
        #pragma unroll
        for (int j = 0; j < 2; j++) {
            int jj = tj * 64 + tx * 4 + 2 * j;
            float lo, hi; unpack2(acc[i][j], lo, hi);
            *(float2*)&Cb[(size_t)ii * NP + jj] = make_float2(lo, hi);
        }
    }
}

// ---------------- xty[b] = F_b^T yc ----------------
__global__ void xty_kernel(const float* __restrict__ y) {
    int b = blockIdx.x, i = threadIdx.x;   // 576 threads
    float2 st = g_stats[b];
    float inv = 1.0f / st.y;
    const float* F = g_bufR + (size_t)b * NC * FW;
    const float* yb = y + b * NC;
    __shared__ float ycs[NC];
    for (int t = i; t < NC; t += NP) ycs[t] = (yb[t] - st.x) * inv;
    __syncthreads();
    float s = 0.0f;
    #pragma unroll 4
    for (int n = 0; n < NC; n++)
        s += F[(size_t)n * FW + i] * ycs[n];
    g_xty[b * NP + i] = s;
}

// ---------------- noise on diag + identity padding ----------------
__global__ void fix_cov_kernel(const float* __restrict__ lnv) {
    int b = blockIdx.x, i = threadIdx.x;   // 576
    float noise = expf(lnv[0]);
    float* d = g_cov + (size_t)b * NP * NP + (size_t)i * NP + i;
    if (i < 513) *d += noise; else *d = 1.0f;
}

// ---------------- Cholesky: diagonal block factor ----------------
__global__ void chol_diag_kernel(int k) {
    __shared__ float D[64][65];
    float* Cb = g_cov + (size_t)blockIdx.x * NP * NP;
    int tid = threadIdx.x;   // 256
    for (int idx = tid; idx < 4096; idx += 256) {
        int i = idx >> 6, j = idx & 63;
        D[i][j] = Cb[(size_t)(k * 64 + i) * NP + k * 64 + j];
    }
    __syncthreads();
    for (int c = 0; c < 64; c++) {
        if (tid == 0) D[c][c] = sqrtf(D[c][c]);
        __syncthreads();
        float dc = D[c][c];
        if (tid > c && tid < 64) D[tid][c] /= dc;
        __syncthreads();
        for (int idx = tid; idx < 4096; idx += 256) {
            int i = idx >> 6, j = idx & 63;
            if (j > c && j <= i) D[i][j] -= D[i][c] * D[j][c];
        }
        __syncthreads();
    }
    for (int idx = tid; idx < 4096; idx += 256) {
        int i = idx >> 6, j = idx & 63;
        Cb[(size_t)(k * 64 + i) * NP + k * 64 + j] = (j <= i) ? D[i][j] : 0.0f;
    }
}

// ---------------- Cholesky: panel triangular solve (one tile per block) ----------------
__global__ void chol_panel_kernel(int k, int ntiles) {
    int bx = blockIdx.x;
    int batch = bx / ntiles;
    int ib = k + 1 + (bx % ntiles);
    float* Cb = g_cov + (size_t)batch * NP * NP;
    __shared__ float D[64][65];
    __shared__ float X[64][65];
    int tid = threadIdx.x;   // 128
    for (int idx = tid; idx < 4096; idx += 128) {
        int i = idx >> 6, j = idx & 63;
        D[i][j] = Cb[(size_t)(k * 64 + i) * NP + k * 64 + j];
        X[i][j] = Cb[(size_t)(ib * 64 + i) * NP + k * 64 + j];
    }
    __syncthreads();
    if (tid < 64) {
        int r = tid;
        for (int c = 0; c < 64; c++) {
            float s = X[r][c];
            for (int j = 0; j < c; j++) s -= X[r][j] * D[c][j];
            X[r][c] = s / D[c][c];
        }
    }
    __syncthreads();
    for (int idx = tid; idx < 4096; idx += 128) {
        int i = idx >> 6, j = idx & 63;
        Cb[(size_t)(ib * 64 + i) * NP + k * 64 + j] = X[i][j];
    }
}

// ---------------- Cholesky: trailing update C[ib][jb] -= L[ib][k] L[jb][k]^T ----------------
__global__ __launch_bounds__(256)
void chol_update_kernel(int k, int npairs) {
    int bx = blockIdx.x;
    int batch = bx / npairs;
    int p = bx % npairs;
    int a = 0;
    while ((a + 1) * (a + 2) / 2 <= p) a++;
    int b2 = p - a * (a + 1) / 2;
    int ib = k + 1 + a, jb = k + 1 + b2;
    float* Cb = g_cov + (size_t)batch * NP * NP;

    __shared__ __align__(16) float LiT[64][68];
    __shared__ __align__(16) float LjT[64][68];
    int tid = threadIdx.x;
    for (int idx = tid; idx < 1024; idx += 256) {
        int r = idx >> 4;
        int c4 = (idx & 15) * 4;
        float4 v = *(const float4*)&Cb[(size_t)(ib * 64 + r) * NP + k * 64 + c4];
        LiT[c4 + 0][r] = v.x; LiT[c4 + 1][r] = v.y; LiT[c4 + 2][r] = v.z; LiT[c4 + 3][r] = v.w;
        float4 u = *(const float4*)&Cb[(size_t)(jb * 64 + r) * NP + k * 64 + c4];
        LjT[c4 + 0][r] = u.x; LjT[c4 + 1][r] = u.y; LjT[c4 + 2][r] = u.z; LjT[c4 + 3][r] = u.w;
    }
    __syncthreads();

    int ty = tid >> 4, tx = tid & 15;
    ull acc[4][2];
    #pragma unroll
    for (int i = 0; i < 4; i++) { acc[i][0] = 0ull; acc[i][1] = 0ull; }

    #pragma unroll 4
    for (int c = 0; c < 64; c++) {
        float4 av = *(const float4*)&LiT[c][ty * 4];
        ulonglong2 bv = *(const ulonglong2*)&LjT[c][tx * 4];
        ull bb[2] = { bv.x, bv.y };
        float a_[4] = { av.x, av.y, av.z, av.w };
        #pragma unroll
        for (int i = 0; i < 4; i++) {
            ull ad = pack2(a_[i], a_[i]);
            acc[i][0] = ffma2(ad, bb[0], acc[i][0]);
            acc[i][1] = ffma2(ad, bb[1], acc[i][1]);
        }
    }

    #pragma unroll
    for (int i = 0; i < 4; i++) {
        int gi = ib * 64 + ty * 4 + i;
        float2* cp = (float2*)&Cb[(size_t)gi * NP + jb * 64 + tx * 4];
        #pragma unroll
        for (int j = 0; j < 2; j++) {
            float lo, hi; unpack2(acc[i][j], lo, hi);
            float2 old = cp[j];
            cp[j] = make_float2(old.x - lo, old.y - hi);
        }
    }
}

// ---------------- triangular solves: L z = xty; L^T w = z ----------------
__global__ void solve_kernel() {
    int b = blockIdx.x, tid = threadIdx.x;  // 256
    const float* L = g_cov + (size_t)b * NP * NP;
    __shared__ float z[NP];
    for (int t = tid; t < NP; t += 256) z[t] = g_xty[b * NP + t];
    __syncthreads();
    int warp = tid >> 5, lane = tid & 31;

    // forward substitution (blocked)
    for (int kb = 0; kb < NBLK; kb++) {
        int i0 = kb * 64;
        if (kb > 0) {
            for (int r = warp; r < 64; r += 8) {
                const float* Lr = L + (size_t)(i0 + r) * NP;
                float s = 0.0f;
                for (int j = lane; j < i0; j += 32) s += Lr[j] * z[j];
                s = warpsum(s);
                if (lane == 0) z[i0 + r] -= s;
            }
        }
        __syncthreads();
        if (warp == 0) {
            for (int c = 0; c < 64; c++) {
                int i = i0 + c;
                float zc = 0.0f;
                if (lane == 0) { zc = z[i] / L[(size_t)i * NP + i]; z[i] = zc; }
                zc = __shfl_sync(0xffffffffu, zc, 0);
                for (int r = c + 1 + lane; r < 64; r += 32)
                    z[i0 + r] -= L[(size_t)(i0 + r) * NP + i] * zc;
                __syncwarp();
            }
        }
        __syncthreads();
    }

    // backward substitution with U = L^T (blocked)
    for (int kb = NBLK - 1; kb >= 0; kb--) {
        int i0 = kb * 64;
        if (kb < NBLK - 1) {
            for (int r = warp; r < 64; r += 8) {
                int i = i0 + r;
                float s = 0.0f;
                for (int j = i0 + 64 + lane; j < NP; j += 32)
                    s += L[(size_t)j * NP + i] * z[j];
                s = warpsum(s);
                if (lane == 0) z[i] -= s;
            }
        }
        __syncthreads();
        if (warp == 0) {
            for (int c = 63; c >= 0; c--) {
                int i = i0 + c;
                float zc = 0.0f;
                if (lane == 0) { zc = z[i] / L[(size_t)i * NP + i]; z[i] = zc; }
                zc = __shfl_sync(0xffffffffu, zc, 0);
                for (int r = lane; r < c; r += 32)
                    z[i0 + r] -= L[(size_t)i * NP + i0 + r] * zc;
                __syncwarp();
            }
        }
        __syncthreads();
    }
    for (int t = tid; t < NP; t += 256) g_w[b * NP + t] = z[t];
}

// ---------------- prediction: y = (tr . w) * std + mean ----------------
__global__ void predict_kernel(float* __restrict__ out) {
    int b = blockIdx.x, chunk = blockIdx.y;
    __shared__ float ws[NP];
    int tid = threadIdx.x;  // 256
    for (int t = tid; t < NP; t += 256) ws[t] = g_w[b * NP + t];
    __syncthreads();
    float2 st = g_stats[b];
    int warp = tid >> 5, lane = tid & 31;
    for (int r = warp; r < 64; r += 8) {
        int m = chunk * 64 + r;
        const float* Fr = g_bufR + (size_t)(BATCH * NC + b * NT + m) * FW;
        float s = 0.0f;
        for (int j = lane; j < NP; j += 32) s += Fr[j] * ws[j];
        s = warpsum(s);
        if (lane == 0) out[b * NT + m] = s * st.y + st.x;
    }
}

// ---------------- launcher ----------------
extern "C" void kernel_launch(void* const* d_in, const int* in_sizes, int n_in,
                              void* d_out, int out_size) {
    const float* xc  = (const float*)d_in[0];
    const float* yc  = (const float*)d_in[1];
    const float* xt  = (const float*)d_in[2];
    const float* W0  = (const float*)d_in[3];
    const float* b0  = (const float*)d_in[4];
    const float* W1  = (const float*)d_in[5];
    const float* b1  = (const float*)d_in[6];
    const float* W2  = (const float*)d_in[7];
    const float* b2  = (const float*)d_in[8];
    const float* Wr  = (const float*)d_in[9];
    const float* br  = (const float*)d_in[10];
    const float* lnv = (const float*)d_in[11];
    float* out = (float*)d_out;

    stats_kernel<<<BATCH, 256>>>(yc);
    layer0_kernel<<<PTS, 128>>>(xc, xt, W0, b0);

    dim3 gg(PTS / BM, HID / BN);
    gemm_kernel<<<gg, 256>>>(0, W1, b1, 1, HID, 1);   // buf1 = sin(buf0@W1+b1)
    gemm_kernel<<<gg, 256>>>(1, W2, b2, 0, HID, 1);   // buf0 = sin(buf1@W2+b2)
    gemm_kernel<<<gg, 256>>>(0, Wr, br, 2, FW, 0);    // bufR = buf0@Wr+br

    padfill_kernel<<<PTS, 64>>>();
    syrk_kernel<<<BATCH * 45, 256>>>();
    xty_kernel<<<BATCH, NP>>>(yc);
    fix_cov_kernel<<<BATCH, NP>>>(lnv);

    for (int k = 0; k < NBLK; k++) {
        chol_diag_kernel<<<BATCH, 256>>>(k);
        int T = NBLK - 1 - k;
        if (T > 0) {
            chol_panel_kernel<<<BATCH * T, 128>>>(k, T);
            int np = T * (T + 1) / 2;
            chol_update_kernel<<<BATCH * np, 256>>>(k, np);
        }
    }

    solve_kernel<<<BATCH, 256>>>();
    predict_kernel<<<dim3(BATCH, NT / 64), 256>>>(out);
}

// round 15
// speedup vs baseline: 2.4417x; 2.4417x over previous
#include <cuda_runtime.h>
#include <cuda_bf16.h>
#include <stdint.h>
#include <math.h>

// ---------------- problem constants ----------------
#define BATCH   64
#define NC      1024
#define NT      1024
#define PTS     (BATCH * (NC + NT))   // 131072
#define HID     512
#define FW      576                   // padded feature width (513 -> 576 = 9*64)
#define NP      576
#define NBLK    9

typedef unsigned long long ull;

// ---------------- scratch (device globals; no allocation allowed) ----------------
__device__ __nv_bfloat16 g_h0[(size_t)PTS * HID];
__device__ __nv_bfloat16 g_l0[(size_t)PTS * HID];
__device__ __nv_bfloat16 g_h1[(size_t)PTS * HID];
__device__ __nv_bfloat16 g_l1[(size_t)PTS * HID];
__device__ __nv_bfloat16 g_wh[3][(size_t)HID * HID];  // W^T high split
__device__ __nv_bfloat16 g_wl[3][(size_t)HID * HID];  // W^T low split
__device__ float  g_bufR[(size_t)PTS * FW];
__device__ float  g_cov[(size_t)BATCH * NP * NP];
__device__ float  g_xty[BATCH * NP];
__device__ float  g_w[BATCH * NP];
__device__ float2 g_stats[BATCH];     // (mean, std)

// ---------------- small helpers ----------------
__device__ __forceinline__ ull pack2(float lo, float hi) {
    ull r; asm("mov.b64 %0, {%1, %2};" : "=l"(r) : "f"(lo), "f"(hi)); return r;
}
__device__ __forceinline__ void unpack2(ull v, float& lo, float& hi) {
    asm("mov.b64 {%0, %1}, %2;" : "=f"(lo), "=f"(hi) : "l"(v));
}
__device__ __forceinline__ ull ffma2(ull a, ull b, ull c) {
    ull d; asm("fma.rn.f32x2 %0, %1, %2, %3;" : "=l"(d) : "l"(a), "l"(b), "l"(c));
    return d;
}
__device__ __forceinline__ float warpsum(float v) {
    #pragma unroll
    for (int o = 16; o; o >>= 1) v += __shfl_xor_sync(0xffffffffu, v, o);
    return v;
}
__device__ __forceinline__ uint32_t s2u32(const void* p) {
    uint32_t a;
    asm("{ .reg .u64 t; cvta.to.shared.u64 t, %1; cvt.u32.u64 %0, t; }" : "=r"(a) : "l"(p));
    return a;
}

// ---------------- mma.sync building blocks (arch-neutral PTX) ----------------
__device__ __forceinline__ void ldsm4(uint32_t* r, uint32_t a) {
    asm volatile("ldmatrix.sync.aligned.m8n8.x4.shared.b16 {%0,%1,%2,%3}, [%4];"
        : "=r"(r[0]), "=r"(r[1]), "=r"(r[2]), "=r"(r[3]) : "r"(a));
}
__device__ __forceinline__ void ldsm2(uint32_t* r, uint32_t a) {
    asm volatile("ldmatrix.sync.aligned.m8n8.x2.shared.b16 {%0,%1}, [%2];"
        : "=r"(r[0]), "=r"(r[1]) : "r"(a));
}
__device__ __forceinline__ void mma16816(float* c, const uint32_t* a, const uint32_t* b) {
    asm volatile("mma.sync.aligned.m16n8k16.row.col.f32.bf16.bf16.f32 "
        "{%0,%1,%2,%3}, {%4,%5,%6,%7}, {%8,%9}, {%0,%1,%2,%3};"
        : "+f"(c[0]), "+f"(c[1]), "+f"(c[2]), "+f"(c[3])
        : "r"(a[0]), "r"(a[1]), "r"(a[2]), "r"(a[3]), "r"(b[0]), "r"(b[1]));
}
#define CP16(saddr, gptr) \
    asm volatile("cp.async.cg.shared.global [%0], [%1], 16;" :: "r"(saddr), "l"(gptr))
#define CP_COMMIT() asm volatile("cp.async.commit_group;")
#define CP_WAIT0()  asm volatile("cp.async.wait_group 0;")

// ---------------- y-context stats (mean, std ddof=1) ----------------
__global__ void stats_kernel(const float* __restrict__ y) {
    int b = blockIdx.x, tid = threadIdx.x;
    double s = 0.0, ss = 0.0;
    for (int n = tid; n < NC; n += 256) {
        double v = (double)y[b * NC + n];
        s += v; ss += v * v;
    }
    #pragma unroll
    for (int o = 16; o; o >>= 1) {
        s  += __shfl_xor_sync(0xffffffffu, s,  o);
        ss += __shfl_xor_sync(0xffffffffu, ss, o);
    }
    __shared__ double sh0[8], sh1[8];
    int w = tid >> 5, l = tid & 31;
    if (l == 0) { sh0[w] = s; sh1[w] = ss; }
    __syncthreads();
    if (tid == 0) {
        double S = 0.0, SS = 0.0;
        for (int i = 0; i < 8; i++) { S += sh0[i]; SS += sh1[i]; }
        double mean = S / (double)NC;
        double var  = (SS - (double)NC * mean * mean) / (double)(NC - 1);
        g_stats[b] = make_float2((float)mean, (float)sqrt(var));
    }
}

// ---------------- weight transpose + bf16 split: WT[n][k] = W[k][n] ----------------
__global__ void wsplit_kernel(const float* __restrict__ W1,
                              const float* __restrict__ W2,
                              const float* __restrict__ Wr) {
    int widx = blockIdx.y;
    const float* W = (widx == 0) ? W1 : ((widx == 1) ? W2 : Wr);
    int n = blockIdx.x;
    int k = threadIdx.x;
    float v = W[(size_t)k * HID + n];
    __nv_bfloat16 h = __float2bfloat16(v);
    float lres = v - __bfloat162float(h);
    g_wh[widx][(size_t)n * HID + k] = h;
    g_wl[widx][(size_t)n * HID + k] = __float2bfloat16(lres);
}

// ---------------- SIREN layer 0 (XD = 1), writes bf16 hi/lo split ----------------
__global__ void layer0_kernel(const float* __restrict__ xc, const float* __restrict__ xt,
                              const float* __restrict__ W0, const float* __restrict__ b0) {
    int p = blockIdx.x;
    float x = (p < BATCH * NC) ? xc[p] : xt[p - BATCH * NC];
    int j = threadIdx.x * 4;
    float4 w = *(const float4*)&W0[j];
    float4 bb = *(const float4*)&b0[j];
    float v[4];
    v[0] = sinf(30.0f * fmaf(x, w.x, bb.x));
    v[1] = sinf(30.0f * fmaf(x, w.y, bb.y));
    v[2] = sinf(30.0f * fmaf(x, w.z, bb.z));
    v[3] = sinf(30.0f * fmaf(x, w.w, bb.w));
    uint32_t hw[2], lw[2];
    #pragma unroll
    for (int i = 0; i < 2; i++) {
        __nv_bfloat16 h0 = __float2bfloat16(v[2 * i]);
        __nv_bfloat16 h1 = __float2bfloat16(v[2 * i + 1]);
        __nv_bfloat16 l0 = __float2bfloat16(v[2 * i] - __bfloat162float(h0));
        __nv_bfloat16 l1 = __float2bfloat16(v[2 * i + 1] - __bfloat162float(h1));
        hw[i] = (uint32_t)__bfloat16_as_ushort(h0) | ((uint32_t)__bfloat16_as_ushort(h1) << 16);
        lw[i] = (uint32_t)__bfloat16_as_ushort(l0) | ((uint32_t)__bfloat16_as_ushort(l1) << 16);
    }
    size_t ob = (size_t)p * HID + j;
    *(uint2*)&g_h0[ob] = make_uint2(hw[0], hw[1]);
    *(uint2*)&g_l0[ob] = make_uint2(lw[0], lw[1]);
}

// ---------------- mma.sync GEMM with bf16-split fp32 emulation ----------------
// C[M x 512] = A[M x 512] @ W[512 x 512] (+bias, optional sin)
// acc += Ah*Wh + Ah*Wl + Al*Wh, fp32 accumulators in registers.
// CTA tile 128x128, BK=32, 8 warps (2m x 4n), warp tile 64x32.
// SMEM per stage: Ah(8K) Al(8K) Bh(8K) Bl(8K) = 32KB; double buffered = 64KB.
#define MMG_STAGE 32768

__global__ __launch_bounds__(256, 1)
void mma_gemm(int aSel, int wIdx, const float* __restrict__ bias, int oSel, int ldc) {
    extern __shared__ __align__(1024) char smem[];
    const uint32_t sb = s2u32(smem);
    const int tid = threadIdx.x;
    const int lane = tid & 31, w = tid >> 5;
    const int wm = w & 1, wn = w >> 1;
    const int n0 = blockIdx.x * 128, m0 = blockIdx.y * 128;

    const __nv_bfloat16* Ah = aSel ? g_h1 : g_h0;
    const __nv_bfloat16* Al = aSel ? g_l1 : g_l0;
    const __nv_bfloat16* src0 = Ah + (size_t)m0 * HID;
    const __nv_bfloat16* src1 = Al + (size_t)m0 * HID;
    const __nv_bfloat16* src2 = g_wh[wIdx] + (size_t)n0 * HID;
    const __nv_bfloat16* src3 = g_wl[wIdx] + (size_t)n0 * HID;

    // cp.async mapping: thread -> (row, 2 consecutive 16B chunks)
    const int lrow = tid >> 1;          // 0..127
    const int lcc  = (tid & 1) * 2;     // chunk 0 or 2
    const int lsw  = (lrow >> 1) & 3;   // swizzle key
    const uint32_t sw0 = (uint32_t)(lrow * 64 + ((lcc ^ lsw) * 16));
    const uint32_t sw1 = (uint32_t)(lrow * 64 + (((lcc + 1) ^ lsw) * 16));
    const size_t goff = (size_t)lrow * HID + (size_t)lcc * 8;

#define ISSUE_STAGE(s, kc) do {                                         \
        uint32_t _b = sb + (uint32_t)(s) * MMG_STAGE;                   \
        const __nv_bfloat16* _g;                                        \
        _g = src0 + goff + (size_t)(kc) * 32;                           \
        CP16(_b + sw0, _g); CP16(_b + sw1, _g + 8);                     \
        _g = src1 + goff + (size_t)(kc) * 32;                           \
        CP16(_b + 8192 + sw0, _g); CP16(_b + 8192 + sw1, _g + 8);       \
        _g = src2 + goff + (size_t)(kc) * 32;                           \
        CP16(_b + 16384 + sw0, _g); CP16(_b + 16384 + sw1, _g + 8);     \
        _g = src3 + goff + (size_t)(kc) * 32;                           \
        CP16(_b + 24576 + sw0, _g); CP16(_b + 24576 + sw1, _g + 8);     \
        CP_COMMIT();                                                    \
    } while (0)

    float acc[4][4][4];
    #pragma unroll
    for (int i = 0; i < 4; i++)
        #pragma unroll
        for (int j = 0; j < 4; j++)
            #pragma unroll
            for (int q = 0; q < 4; q++) acc[i][j][q] = 0.0f;

    // ldmatrix lane addressing
    const int rA  = ((lane >> 3) & 1) * 8 + (lane & 7);  // row within 16-row tile
    const int cAh = lane >> 4;                            // k-chunk offset (0/1)
    const int idxb = lane & 15;
    const int rB  = idxb & 7;
    const int cBh = (idxb >> 3) & 1;

    ISSUE_STAGE(0, 0);
    CP_WAIT0();
    __syncthreads();

    for (int t = 0; t < 16; ++t) {
        if (t < 15) ISSUE_STAGE((t + 1) & 1, t + 1);
        uint32_t base = sb + (uint32_t)(t & 1) * MMG_STAGE;
        #pragma unroll
        for (int ks = 0; ks < 2; ++ks) {
            int kb = ks * 2;
            uint32_t ahf[4][4], alf[4][4], bhf[4][2], blf[4][2];
            #pragma unroll
            for (int mt = 0; mt < 4; ++mt) {
                int rowA = wm * 64 + mt * 16 + rA;
                uint32_t ad = base + (uint32_t)(rowA * 64 +
                              (((kb + cAh) ^ ((rowA >> 1) & 3)) * 16));
                ldsm4(ahf[mt], ad);
                ldsm4(alf[mt], ad + 8192);
            }
            #pragma unroll
            for (int nt = 0; nt < 4; ++nt) {
                int rowB = wn * 32 + nt * 8 + rB;
                uint32_t bd = base + 16384u + (uint32_t)(rowB * 64 +
                              (((kb + cBh) ^ ((rowB >> 1) & 3)) * 16));
                ldsm2(bhf[nt], bd);
                ldsm2(blf[nt], bd + 8192);
            }
            #pragma unroll
            for (int mt = 0; mt < 4; ++mt)
                #pragma unroll
                for (int nt = 0; nt < 4; ++nt) {
                    mma16816(acc[mt][nt], ahf[mt], bhf[nt]);
                    mma16816(acc[mt][nt], ahf[mt], blf[nt]);
                    mma16816(acc[mt][nt], alf[mt], bhf[nt]);
                }
        }
        if (t < 15) {
            CP_WAIT0();
            __syncthreads();
        }
    }
#undef ISSUE_STAGE

    // ---------------- epilogue ----------------
    const int rbase = m0 + wm * 64 + (lane >> 2);
    const int cbase = n0 + wn * 32 + 2 * (lane & 3);
    __nv_bfloat16* Oh = oSel ? g_h0 : g_h1;
    __nv_bfloat16* Ol = oSel ? g_l0 : g_l1;

    #pragma unroll
    for (int nt = 0; nt < 4; ++nt) {
        int col = cbase + nt * 8;
        float b0v = bias[col], b1v = bias[col + 1];
        #pragma unroll
        for (int mt = 0; mt < 4; ++mt) {
            int rr0 = rbase + mt * 16;
            int rr1 = rr0 + 8;
            float v00 = acc[mt][nt][0] + b0v;
            float v01 = acc[mt][nt][1] + b1v;
            float v10 = acc[mt][nt][2] + b0v;
            float v11 = acc[mt][nt][3] + b1v;
            if (oSel == 2) {
                *(float2*)&g_bufR[(size_t)rr0 * ldc + col] = make_float2(v00, v01);
                *(float2*)&g_bufR[(size_t)rr1 * ldc + col] = make_float2(v10, v11);
            } else {
                float s00 = sinf(v00), s01 = sinf(v01);
                float s10 = sinf(v10), s11 = sinf(v11);
                __nv_bfloat16 h00 = __float2bfloat16(s00), h01 = __float2bfloat16(s01);
                __nv_bfloat16 h10 = __float2bfloat16(s10), h11 = __float2bfloat16(s11);
                __nv_bfloat16 l00 = __float2bfloat16(s00 - __bfloat162float(h00));
                __nv_bfloat16 l01 = __float2bfloat16(s01 - __bfloat162float(h01));
                __nv_bfloat16 l10 = __float2bfloat16(s10 - __bfloat162float(h10));
                __nv_bfloat16 l11 = __float2bfloat16(s11 - __bfloat162float(h11));
                uint32_t ph0 = (uint32_t)__bfloat16_as_ushort(h00) |
                               ((uint32_t)__bfloat16_as_ushort(h01) << 16);
                uint32_t pl0 = (uint32_t)__bfloat16_as_ushort(l00) |
                               ((uint32_t)__bfloat16_as_ushort(l01) << 16);
                uint32_t ph1 = (uint32_t)__bfloat16_as_ushort(h10) |
                               ((uint32_t)__bfloat16_as_ushort(h11) << 16);
                uint32_t pl1 = (uint32_t)__bfloat16_as_ushort(l10) |
                               ((uint32_t)__bfloat16_as_ushort(l11) << 16);
                *(uint32_t*)&Oh[(size_t)rr0 * HID + col] = ph0;
                *(uint32_t*)&Ol[(size_t)rr0 * HID + col] = pl0;
                *(uint32_t*)&Oh[(size_t)rr1 * HID + col] = ph1;
                *(uint32_t*)&Ol[(size_t)rr1 * HID + col] = pl1;
            }
        }
    }
}

// ---------------- pad feature cols: col 512 = 1, cols 513..575 = 0 ----------------
__global__ void padfill_kernel() {
    size_t p = blockIdx.x;
    int t = threadIdx.x;     // 64
    g_bufR[p * FW + HID + t] = (t == 0) ? 1.0f : 0.0f;
}

// ---------------- batched SYRK: cov[b] = F_b^T F_b (lower tiles only) ----------------
__global__ __launch_bounds__(256)
void syrk_kernel() {
    int bx = blockIdx.x;
    int batch = bx / 45;
    int p = bx % 45;
    int ti = 0;
    while ((ti + 1) * (ti + 2) / 2 <= p) ti++;
    int tj = p - ti * (ti + 1) / 2;

    const float* F = g_bufR + (size_t)batch * NC * FW;
    __shared__ __align__(16) float Sa[2][16][64];
    __shared__ __align__(16) float Sb[2][16][64];

    int tid = threadIdx.x;
    int lr = tid >> 4;
    int lc = (tid & 15) * 4;
    const float* Fa = F + (size_t)lr * FW + ti * 64 + lc;
    const float* Fb = F + (size_t)lr * FW + tj * 64 + lc;

    float4 ra = *(const float4*)Fa;
    float4 rb = *(const float4*)Fb;
    *(float4*)&Sa[0][lr][lc] = ra;
    *(float4*)&Sb[0][lr][lc] = rb;
    __syncthreads();

    ull acc[4][2];
    #pragma unroll
    for (int i = 0; i < 4; i++) { acc[i][0] = 0ull; acc[i][1] = 0ull; }

    int ty = tid >> 4, tx = tid & 15;
    int buf = 0;
    for (int t = 0; t < 64; ++t) {
        if (t + 1 < 64) {
            ra = *(const float4*)(Fa + (size_t)(t + 1) * 16 * FW);
            rb = *(const float4*)(Fb + (size_t)(t + 1) * 16 * FW);
        }
        #pragma unroll
        for (int kk = 0; kk < 16; ++kk) {
            float4 av = *(const float4*)&Sa[buf][kk][ty * 4];
            ulonglong2 bv = *(const ulonglong2*)&Sb[buf][kk][tx * 4];
            ull bb[2] = { bv.x, bv.y };
            float a_[4] = { av.x, av.y, av.z, av.w };
            #pragma unroll
            for (int i = 0; i < 4; i++) {
                ull ad = pack2(a_[i], a_[i]);
                acc[i][0] = ffma2(ad, bb[0], acc[i][0]);
                acc[i][1] = ffma2(ad, bb[1], acc[i][1]);
            }
        }
        if (t + 1 < 64) {
            __syncthreads();
            int nb = buf ^ 1;
            *(float4*)&Sa[nb][lr][lc] = ra;
            *(float4*)&Sb[nb][lr][lc] = rb;
            __syncthreads();
            buf = nb;
        }
    }

    float* Cb = g_cov + (size_t)batch * NP * NP;
    #pragma unroll
    for (int i = 0; i < 4; i++) {
        int ii = ti * 64 + ty * 4 + i;
        #pragma unroll
        for (int j = 0; j < 2; j++) {
            int jj = tj * 64 + tx * 4 + 2 * j;
            float lo, hi; unpack2(acc[i][j], lo, hi);
            *(float2*)&Cb[(size_t)ii * NP + jj] = make_float2(lo, hi);
        }
    }
}

// ---------------- xty[b] = F_b^T yc ----------------
__global__ void xty_kernel(const float* __restrict__ y) {
    int b = blockIdx.x, i = threadIdx.x;   // 576 threads
    float2 st = g_stats[b];
    float inv = 1.0f / st.y;
    const float* F = g_bufR + (size_t)b * NC * FW;
    const float* yb = y + b * NC;
    __shared__ float ycs[NC];
    for (int t = i; t < NC; t += NP) ycs[t] = (yb[t] - st.x) * inv;
    __syncthreads();
    float s = 0.0f;
    #pragma unroll 4
    for (int n = 0; n < NC; n++)
        s += F[(size_t)n * FW + i] * ycs[n];
    g_xty[b * NP + i] = s;
}

// ---------------- noise on diag + identity padding ----------------
__global__ void fix_cov_kernel(const float* __restrict__ lnv) {
    int b = blockIdx.x, i = threadIdx.x;   // 576
    float noise = expf(lnv[0]);
    float* d = g_cov + (size_t)b * NP * NP + (size_t)i * NP + i;
    if (i < 513) *d += noise; else *d = 1.0f;
}

// ---------------- Cholesky: diagonal block factor ----------------
__global__ void chol_diag_kernel(int k) {
    __shared__ float D[64][65];
    float* Cb = g_cov + (size_t)blockIdx.x * NP * NP;
    int tid = threadIdx.x;   // 256
    for (int idx = tid; idx < 4096; idx += 256) {
        int i = idx >> 6, j = idx & 63;
        D[i][j] = Cb[(size_t)(k * 64 + i) * NP + k * 64 + j];
    }
    __syncthreads();
    for (int c = 0; c < 64; c++) {
        if (tid == 0) D[c][c] = sqrtf(D[c][c]);
        __syncthreads();
        float dc = D[c][c];
        if (tid > c && tid < 64) D[tid][c] /= dc;
        __syncthreads();
        for (int idx = tid; idx < 4096; idx += 256) {
            int i = idx >> 6, j = idx & 63;
            if (j > c && j <= i) D[i][j] -= D[i][c] * D[j][c];
        }
        __syncthreads();
    }
    for (int idx = tid; idx < 4096; idx += 256) {
        int i = idx >> 6, j = idx & 63;
        Cb[(size_t)(k * 64 + i) * NP + k * 64 + j] = (j <= i) ? D[i][j] : 0.0f;
    }
}

// ---------------- Cholesky: panel triangular solve ----------------
__global__ void chol_panel_kernel(int k, int ntiles) {
    int bx = blockIdx.x;
    int batch = bx / ntiles;
    int ib = k + 1 + (bx % ntiles);
    float* Cb = g_cov + (size_t)batch * NP * NP;
    __shared__ float D[64][65];
    __shared__ float X[64][65];
    int tid = threadIdx.x;   // 128
    for (int idx = tid; idx < 4096; idx += 128) {
        int i = idx >> 6, j = idx & 63;
        D[i][j] = Cb[(size_t)(k * 64 + i) * NP + k * 64 + j];
        X[i][j] = Cb[(size_t)(ib * 64 + i) * NP + k * 64 + j];
    }
    __syncthreads();
    if (tid < 64) {
        int r = tid;
        for (int c = 0; c < 64; c++) {
            float s = X[r][c];
            for (int j = 0; j < c; j++) s -= X[r][j] * D[c][j];
            X[r][c] = s / D[c][c];
        }
    }
    __syncthreads();
    for (int idx = tid; idx < 4096; idx += 128) {
        int i = idx >> 6, j = idx & 63;
        Cb[(size_t)(ib * 64 + i) * NP + k * 64 + j] = X[i][j];
    }
}

// ---------------- Cholesky: trailing update ----------------
__global__ __launch_bounds__(256)
void chol_update_kernel(int k, int npairs) {
    int bx = blockIdx.x;
    int batch = bx / npairs;
    int p = bx % npairs;
    int a = 0;
    while ((a + 1) * (a + 2) / 2 <= p) a++;
    int b2 = p - a * (a + 1) / 2;
    int ib = k + 1 + a, jb = k + 1 + b2;
    float* Cb = g_cov + (size_t)batch * NP * NP;

    __shared__ __align__(16) float LiT[64][68];
    __shared__ __align__(16) float LjT[64][68];
    int tid = threadIdx.x;
    for (int idx = tid; idx < 1024; idx += 256) {
        int r = idx >> 4;
        int c4 = (idx & 15) * 4;
        float4 v = *(const float4*)&Cb[(size_t)(ib * 64 + r) * NP + k * 64 + c4];
        LiT[c4 + 0][r] = v.x; LiT[c4 + 1][r] = v.y; LiT[c4 + 2][r] = v.z; LiT[c4 + 3][r] = v.w;
        float4 u = *(const float4*)&Cb[(size_t)(jb * 64 + r) * NP + k * 64 + c4];
        LjT[c4 + 0][r] = u.x; LjT[c4 + 1][r] = u.y; LjT[c4 + 2][r] = u.z; LjT[c4 + 3][r] = u.w;
    }
    __syncthreads();

    int ty = tid >> 4, tx = tid & 15;
    ull acc[4][2];
    #pragma unroll
    for (int i = 0; i < 4; i++) { acc[i][0] = 0ull; acc[i][1] = 0ull; }

    #pragma unroll 4
    for (int c = 0; c < 64; c++) {
        float4 av = *(const float4*)&LiT[c][ty * 4];
        ulonglong2 bv = *(const ulonglong2*)&LjT[c][tx * 4];
        ull bb[2] = { bv.x, bv.y };
        float a_[4] = { av.x, av.y, av.z, av.w };
        #pragma unroll
        for (int i = 0; i < 4; i++) {
            ull ad = pack2(a_[i], a_[i]);
            acc[i][0] = ffma2(ad, bb[0], acc[i][0]);
            acc[i][1] = ffma2(ad, bb[1], acc[i][1]);
        }
    }

    #pragma unroll
    for (int i = 0; i < 4; i++) {
        int gi = ib * 64 + ty * 4 + i;
        float2* cp = (float2*)&Cb[(size_t)gi * NP + jb * 64 + tx * 4];
        #pragma unroll
        for (int j = 0; j < 2; j++) {
            float lo, hi; unpack2(acc[i][j], lo, hi);
            float2 old = cp[j];
            cp[j] = make_float2(old.x - lo, old.y - hi);
        }
    }
}

// ---------------- triangular solves: L z = xty; L^T w = z ----------------
__global__ void solve_kernel() {
    int b = blockIdx.x, tid = threadIdx.x;  // 256
    const float* L = g_cov + (size_t)b * NP * NP;
    __shared__ float z[NP];
    for (int t = tid; t < NP; t += 256) z[t] = g_xty[b * NP + t];
    __syncthreads();
    int warp = tid >> 5, lane = tid & 31;

    for (int kb = 0; kb < NBLK; kb++) {
        int i0 = kb * 64;
        if (kb > 0) {
            for (int r = warp; r < 64; r += 8) {
                const float* Lr = L + (size_t)(i0 + r) * NP;
                float s = 0.0f;
                for (int j = lane; j < i0; j += 32) s += Lr[j] * z[j];
                s = warpsum(s);
                if (lane == 0) z[i0 + r] -= s;
            }
        }
        __syncthreads();
        if (warp == 0) {
            for (int c = 0; c < 64; c++) {
                int i = i0 + c;
                float zc = 0.0f;
                if (lane == 0) { zc = z[i] / L[(size_t)i * NP + i]; z[i] = zc; }
                zc = __shfl_sync(0xffffffffu, zc, 0);
                for (int r = c + 1 + lane; r < 64; r += 32)
                    z[i0 + r] -= L[(size_t)(i0 + r) * NP + i] * zc;
                __syncwarp();
            }
        }
        __syncthreads();
    }

    for (int kb = NBLK - 1; kb >= 0; kb--) {
        int i0 = kb * 64;
        if (kb < NBLK - 1) {
            for (int r = warp; r < 64; r += 8) {
                int i = i0 + r;
                float s = 0.0f;
                for (int j = i0 + 64 + lane; j < NP; j += 32)
                    s += L[(size_t)j * NP + i] * z[j];
                s = warpsum(s);
                if (lane == 0) z[i] -= s;
            }
        }
        __syncthreads();
        if (warp == 0) {
            for (int c = 63; c >= 0; c--) {
                int i = i0 + c;
                float zc = 0.0f;
                if (lane == 0) { zc = z[i] / L[(size_t)i * NP + i]; z[i] = zc; }
                zc = __shfl_sync(0xffffffffu, zc, 0);
                for (int r = lane; r < c; r += 32)
                    z[i0 + r] -= L[(size_t)i * NP + i0 + r] * zc;
                __syncwarp();
            }
        }
        __syncthreads();
    }
    for (int t = tid; t < NP; t += 256) g_w[b * NP + t] = z[t];
}

// ---------------- prediction: y = (tr . w) * std + mean ----------------
__global__ void predict_kernel(float* __restrict__ out) {
    int b = blockIdx.x, chunk = blockIdx.y;
    __shared__ float ws[NP];
    int tid = threadIdx.x;  // 256
    for (int t = tid; t < NP; t += 256) ws[t] = g_w[b * NP + t];
    __syncthreads();
    float2 st = g_stats[b];
    int warp = tid >> 5, lane = tid & 31;
    for (int r = warp; r < 64; r += 8) {
        int m = chunk * 64 + r;
        const float* Fr = g_bufR + (size_t)(BATCH * NC + b * NT + m) * FW;
        float s = 0.0f;
        for (int j = lane; j < NP; j += 32) s += Fr[j] * ws[j];
        s = warpsum(s);
        if (lane == 0) out[b * NT + m] = s * st.y + st.x;
    }
}

// ---------------- launcher ----------------
extern "C" void kernel_launch(void* const* d_in, const int* in_sizes, int n_in,
                              void* d_out, int out_size) {
    const float* xc  = (const float*)d_in[0];
    const float* yc  = (const float*)d_in[1];
    const float* xt  = (const float*)d_in[2];
    const float* W0  = (const float*)d_in[3];
    const float* b0  = (const float*)d_in[4];
    const float* W1  = (const float*)d_in[5];
    const float* b1  = (const float*)d_in[6];
    const float* W2  = (const float*)d_in[7];
    const float* b2  = (const float*)d_in[8];
    const float* Wr  = (const float*)d_in[9];
    const float* br  = (const float*)d_in[10];
    const float* lnv = (const float*)d_in[11];
    float* out = (float*)d_out;

    cudaFuncSetAttribute(mma_gemm, cudaFuncAttributeMaxDynamicSharedMemorySize,
                         2 * MMG_STAGE);

    stats_kernel<<<BATCH, 256>>>(yc);
    wsplit_kernel<<<dim3(HID, 3), HID>>>(W1, W2, Wr);
    layer0_kernel<<<PTS, 128>>>(xc, xt, W0, b0);

    dim3 gg(4, PTS / 128);   // x = N-blocks (fast) so A tiles are reused in L2
    mma_gemm<<<gg, 256, 2 * MMG_STAGE>>>(0, 0, b1, 0, HID);   // (h0,l0) -> (h1,l1), sin
    mma_gemm<<<gg, 256, 2 * MMG_STAGE>>>(1, 1, b2, 1, HID);   // (h1,l1) -> (h0,l0), sin
    mma_gemm<<<gg, 256, 2 * MMG_STAGE>>>(0, 2, br, 2, FW);    // (h0,l0) -> bufR (f32)

    padfill_kernel<<<PTS, 64>>>();
    syrk_kernel<<<BATCH * 45, 256>>>();
    xty_kernel<<<BATCH, NP>>>(yc);
    fix_cov_kernel<<<BATCH, NP>>>(lnv);

    for (int k = 0; k < NBLK; k++) {
        chol_diag_kernel<<<BATCH, 256>>>(k);
        int T = NBLK - 1 - k;
        if (T > 0) {
            chol_panel_kernel<<<BATCH * T, 128>>>(k, T);
            int np = T * (T + 1) / 2;
            chol_update_kernel<<<BATCH * np, 256>>>(k, np);
        }
    }

    solve_kernel<<<BATCH, 256>>>();
    predict_kernel<<<dim3(BATCH, NT / 64), 256>>>(out);
}

// round 17
// speedup vs baseline: 2.4834x; 1.0171x over previous
#include <cuda_runtime.h>
#include <cuda_bf16.h>
#include <stdint.h>
#include <math.h>

// ---------------- problem constants ----------------
#define BATCH   64
#define NC      1024
#define NT      1024
#define PTS     (BATCH * (NC + NT))   // 131072
#define HID     512
#define FW      576                   // padded feature width (513 -> 576 = 9*64)
#define NP      576
#define NBLK    9

typedef unsigned long long ull;

// ---------------- scratch (device globals; no allocation allowed) ----------------
__device__ __nv_bfloat16 g_h0[(size_t)PTS * HID];
__device__ __nv_bfloat16 g_l0[(size_t)PTS * HID];
__device__ __nv_bfloat16 g_h1[(size_t)PTS * HID];
__device__ __nv_bfloat16 g_l1[(size_t)PTS * HID];
__device__ __nv_bfloat16 g_wh[3][(size_t)HID * HID];  // W^T high split
__device__ __nv_bfloat16 g_wl[3][(size_t)HID * HID];  // W^T low split
__device__ __nv_bfloat16 g_fh[(size_t)PTS * FW];      // features hi (row-major)
__device__ __nv_bfloat16 g_fl[(size_t)PTS * FW];      // features lo
__device__ __nv_bfloat16 g_fhT[(size_t)BATCH * FW * NC];  // context features^T hi
__device__ __nv_bfloat16 g_flT[(size_t)BATCH * FW * NC];  // context features^T lo
__device__ float  g_cov[(size_t)BATCH * NP * NP];
__device__ float  g_xty[BATCH * NP];
__device__ float  g_w[BATCH * NP];
__device__ float2 g_stats[BATCH];     // (mean, std)

// ---------------- small helpers ----------------
__device__ __forceinline__ float warpsum(float v) {
    #pragma unroll
    for (int o = 16; o; o >>= 1) v += __shfl_xor_sync(0xffffffffu, v, o);
    return v;
}
__device__ __forceinline__ uint32_t s2u32(const void* p) {
    uint32_t a;
    asm("{ .reg .u64 t; cvta.to.shared.u64 t, %1; cvt.u32.u64 %0, t; }" : "=r"(a) : "l"(p));
    return a;
}

// ---------------- mma.sync building blocks (arch-neutral PTX) ----------------
__device__ __forceinline__ void ldsm4(uint32_t* r, uint32_t a) {
    asm volatile("ldmatrix.sync.aligned.m8n8.x4.shared.b16 {%0,%1,%2,%3}, [%4];"
        : "=r"(r[0]), "=r"(r[1]), "=r"(r[2]), "=r"(r[3]) : "r"(a));
}
__device__ __forceinline__ void ldsm2(uint32_t* r, uint32_t a) {
    asm volatile("ldmatrix.sync.aligned.m8n8.x2.shared.b16 {%0,%1}, [%2];"
        : "=r"(r[0]), "=r"(r[1]) : "r"(a));
}
__device__ __forceinline__ void mma16816(float* c, const uint32_t* a, const uint32_t* b) {
    asm volatile("mma.sync.aligned.m16n8k16.row.col.f32.bf16.bf16.f32 "
        "{%0,%1,%2,%3}, {%4,%5,%6,%7}, {%8,%9}, {%0,%1,%2,%3};"
        : "+f"(c[0]), "+f"(c[1]), "+f"(c[2]), "+f"(c[3])
        : "r"(a[0]), "r"(a[1]), "r"(a[2]), "r"(a[3]), "r"(b[0]), "r"(b[1]));
}
#define CP16(saddr, gptr) \
    asm volatile("cp.async.cg.shared.global [%0], [%1], 16;" :: "r"(saddr), "l"(gptr))
#define CP_COMMIT() asm volatile("cp.async.commit_group;")
#define CP_WAIT0()  asm volatile("cp.async.wait_group 0;")
#define CP_WAIT1()  asm volatile("cp.async.wait_group 1;")

// ---------------- y-context stats (mean, std ddof=1) ----------------
__global__ void stats_kernel(const float* __restrict__ y) {
    int b = blockIdx.x, tid = threadIdx.x;
    double s = 0.0, ss = 0.0;
    for (int n = tid; n < NC; n += 256) {
        double v = (double)y[b * NC + n];
        s += v; ss += v * v;
    }
    #pragma unroll
    for (int o = 16; o; o >>= 1) {
        s  += __shfl_xor_sync(0xffffffffu, s,  o);
        ss += __shfl_xor_sync(0xffffffffu, ss, o);
    }
    __shared__ double sh0[8], sh1[8];
    int w = tid >> 5, l = tid & 31;
    if (l == 0) { sh0[w] = s; sh1[w] = ss; }
    __syncthreads();
    if (tid == 0) {
        double S = 0.0, SS = 0.0;
        for (int i = 0; i < 8; i++) { S += sh0[i]; SS += sh1[i]; }
        double mean = S / (double)NC;
        double var  = (SS - (double)NC * mean * mean) / (double)(NC - 1);
        g_stats[b] = make_float2((float)mean, (float)sqrt(var));
    }
}

// ---------------- weight transpose + bf16 split: WT[n][k] = W[k][n] ----------------
__global__ void wsplit_kernel(const float* __restrict__ W1,
                              const float* __restrict__ W2,
                              const float* __restrict__ Wr) {
    int widx = blockIdx.y;
    const float* W = (widx == 0) ? W1 : ((widx == 1) ? W2 : Wr);
    int n = blockIdx.x;
    int k = threadIdx.x;
    float v = W[(size_t)k * HID + n];
    __nv_bfloat16 h = __float2bfloat16(v);
    float lres = v - __bfloat162float(h);
    g_wh[widx][(size_t)n * HID + k] = h;
    g_wl[widx][(size_t)n * HID + k] = __float2bfloat16(lres);
}

// ---------------- SIREN layer 0 (XD = 1), writes bf16 hi/lo split ----------------
__global__ void layer0_kernel(const float* __restrict__ xc, const float* __restrict__ xt,
                              const float* __restrict__ W0, const float* __restrict__ b0) {
    int p = blockIdx.x;
    float x = (p < BATCH * NC) ? xc[p] : xt[p - BATCH * NC];
    int j = threadIdx.x * 4;
    float4 w = *(const float4*)&W0[j];
    float4 bb = *(const float4*)&b0[j];
    float v[4];
    v[0] = sinf(30.0f * fmaf(x, w.x, bb.x));
    v[1] = sinf(30.0f * fmaf(x, w.y, bb.y));
    v[2] = sinf(30.0f * fmaf(x, w.z, bb.z));
    v[3] = sinf(30.0f * fmaf(x, w.w, bb.w));
    uint32_t hw[2], lw[2];
    #pragma unroll
    for (int i = 0; i < 2; i++) {
        __nv_bfloat16 h0 = __float2bfloat16(v[2 * i]);
        __nv_bfloat16 h1 = __float2bfloat16(v[2 * i + 1]);
        __nv_bfloat16 l0 = __float2bfloat16(v[2 * i] - __bfloat162float(h0));
        __nv_bfloat16 l1 = __float2bfloat16(v[2 * i + 1] - __bfloat162float(h1));
        hw[i] = (uint32_t)__bfloat16_as_ushort(h0) | ((uint32_t)__bfloat16_as_ushort(h1) << 16);
        lw[i] = (uint32_t)__bfloat16_as_ushort(l0) | ((uint32_t)__bfloat16_as_ushort(l1) << 16);
    }
    size_t ob = (size_t)p * HID + j;
    *(uint2*)&g_h0[ob] = make_uint2(hw[0], hw[1]);
    *(uint2*)&g_l0[ob] = make_uint2(lw[0], lw[1]);
}

// ---------------- mma.sync GEMM with bf16-split fp32 emulation ----------------
// acc += Ah*Wh + Ah*Wl + Al*Wh, fp32 accumulators in registers.
// CTA tile 128x128, BK=32, 8 warps (2m x 4n), warp tile 64x32. 3-stage cp.async.
#define MMG_STAGE 32768

__global__ __launch_bounds__(256, 1)
void mma_gemm(int aSel, int wIdx, const float* __restrict__ bias, int oSel, int ldc,
              int applySin) {
    extern __shared__ __align__(1024) char smem[];
    const uint32_t sb = s2u32(smem);
    const int tid = threadIdx.x;
    const int lane = tid & 31, w = tid >> 5;
    const int wm = w & 1, wn = w >> 1;
    const int n0 = blockIdx.x * 128, m0 = blockIdx.y * 128;

    const __nv_bfloat16* Ah = aSel ? g_h1 : g_h0;
    const __nv_bfloat16* Al = aSel ? g_l1 : g_l0;
    const __nv_bfloat16* src0 = Ah + (size_t)m0 * HID;
    const __nv_bfloat16* src1 = Al + (size_t)m0 * HID;
    const __nv_bfloat16* src2 = g_wh[wIdx] + (size_t)n0 * HID;
    const __nv_bfloat16* src3 = g_wl[wIdx] + (size_t)n0 * HID;

    const int lrow = tid >> 1;
    const int lcc  = (tid & 1) * 2;
    const int lsw  = (lrow >> 1) & 3;
    const uint32_t sw0 = (uint32_t)(lrow * 64 + ((lcc ^ lsw) * 16));
    const uint32_t sw1 = (uint32_t)(lrow * 64 + (((lcc + 1) ^ lsw) * 16));
    const size_t goff = (size_t)lrow * HID + (size_t)lcc * 8;

#define ISSUE_STAGE(s, kc) do {                                         \
        uint32_t _b = sb + (uint32_t)(s) * MMG_STAGE;                   \
        const __nv_bfloat16* _g;                                        \
        _g = src0 + goff + (size_t)(kc) * 32;                           \
        CP16(_b + sw0, _g); CP16(_b + sw1, _g + 8);                     \
        _g = src1 + goff + (size_t)(kc) * 32;                           \
        CP16(_b + 8192 + sw0, _g); CP16(_b + 8192 + sw1, _g + 8);       \
        _g = src2 + goff + (size_t)(kc) * 32;                           \
        CP16(_b + 16384 + sw0, _g); CP16(_b + 16384 + sw1, _g + 8);     \
        _g = src3 + goff + (size_t)(kc) * 32;                           \
        CP16(_b + 24576 + sw0, _g); CP16(_b + 24576 + sw1, _g + 8);     \
        CP_COMMIT();                                                    \
    } while (0)

    float acc[4][4][4];
    #pragma unroll
    for (int i = 0; i < 4; i++)
        #pragma unroll
        for (int j = 0; j < 4; j++)
            #pragma unroll
            for (int q = 0; q < 4; q++) acc[i][j][q] = 0.0f;

    const int rA  = ((lane >> 3) & 1) * 8 + (lane & 7);
    const int cAh = lane >> 4;
    const int idxb = lane & 15;
    const int rB  = idxb & 7;
    const int cBh = (idxb >> 3) & 1;

    ISSUE_STAGE(0, 0);
    ISSUE_STAGE(1, 1);

    for (int t = 0; t < 16; ++t) {
        if (t == 15) { CP_WAIT0(); } else { CP_WAIT1(); }
        __syncthreads();
        if (t + 2 < 16) {
            int s2 = (t + 2) % 3;
            ISSUE_STAGE(s2, t + 2);
        }
        uint32_t base = sb + (uint32_t)(t % 3) * MMG_STAGE;
        #pragma unroll
        for (int ks = 0; ks < 2; ++ks) {
            int kb = ks * 2;
            uint32_t ahf[4][4], alf[4][4], bhf[4][2], blf[4][2];
            #pragma unroll
            for (int mt = 0; mt < 4; ++mt) {
                int rowA = wm * 64 + mt * 16 + rA;
                uint32_t ad = base + (uint32_t)(rowA * 64 +
                              (((kb + cAh) ^ ((rowA >> 1) & 3)) * 16));
                ldsm4(ahf[mt], ad);
                ldsm4(alf[mt], ad + 8192);
            }
            #pragma unroll
            for (int nt = 0; nt < 4; ++nt) {
                int rowB = wn * 32 + nt * 8 + rB;
                uint32_t bd = base + 16384u + (uint32_t)(rowB * 64 +
                              (((kb + cBh) ^ ((rowB >> 1) & 3)) * 16));
                ldsm2(bhf[nt], bd);
                ldsm2(blf[nt], bd + 8192);
            }
            #pragma unroll
            for (int mt = 0; mt < 4; ++mt)
                #pragma unroll
                for (int nt = 0; nt < 4; ++nt) {
                    mma16816(acc[mt][nt], ahf[mt], bhf[nt]);
                    mma16816(acc[mt][nt], ahf[mt], blf[nt]);
                    mma16816(acc[mt][nt], alf[mt], bhf[nt]);
                }
        }
    }
#undef ISSUE_STAGE

    // ---------------- epilogue: bias (+sin), write bf16 hi/lo split ----------------
    const int rbase = m0 + wm * 64 + (lane >> 2);
    const int cbase = n0 + wn * 32 + 2 * (lane & 3);
    __nv_bfloat16* Oh = (oSel == 2) ? g_fh : (oSel ? g_h0 : g_h1);
    __nv_bfloat16* Ol = (oSel == 2) ? g_fl : (oSel ? g_l0 : g_l1);

    #pragma unroll
    for (int nt = 0; nt < 4; ++nt) {
        int col = cbase + nt * 8;
        float b0v = bias[col], b1v = bias[col + 1];
        #pragma unroll
        for (int mt = 0; mt < 4; ++mt) {
            int rr0 = rbase + mt * 16;
            int rr1 = rr0 + 8;
            float v00 = acc[mt][nt][0] + b0v;
            float v01 = acc[mt][nt][1] + b1v;
            float v10 = acc[mt][nt][2] + b0v;
            float v11 = acc[mt][nt][3] + b1v;
            if (applySin) {
                v00 = sinf(v00); v01 = sinf(v01);
                v10 = sinf(v10); v11 = sinf(v11);
            }
            __nv_bfloat16 h00 = __float2bfloat16(v00), h01 = __float2bfloat16(v01);
            __nv_bfloat16 h10 = __float2bfloat16(v10), h11 = __float2bfloat16(v11);
            __nv_bfloat16 l00 = __float2bfloat16(v00 - __bfloat162float(h00));
            __nv_bfloat16 l01 = __float2bfloat16(v01 - __bfloat162float(h01));
            __nv_bfloat16 l10 = __float2bfloat16(v10 - __bfloat162float(h10));
            __nv_bfloat16 l11 = __float2bfloat16(v11 - __bfloat162float(h11));
            uint32_t ph0 = (uint32_t)__bfloat16_as_ushort(h00) |
                           ((uint32_t)__bfloat16_as_ushort(h01) << 16);
            uint32_t pl0 = (uint32_t)__bfloat16_as_ushort(l00) |
                           ((uint32_t)__bfloat16_as_ushort(l01) << 16);
            uint32_t ph1 = (uint32_t)__bfloat16_as_ushort(h10) |
                           ((uint32_t)__bfloat16_as_ushort(h11) << 16);
            uint32_t pl1 = (uint32_t)__bfloat16_as_ushort(l10) |
                           ((uint32_t)__bfloat16_as_ushort(l11) << 16);
            *(uint32_t*)&Oh[(size_t)rr0 * ldc + col] = ph0;
            *(uint32_t*)&Ol[(size_t)rr0 * ldc + col] = pl0;
            *(uint32_t*)&Oh[(size_t)rr1 * ldc + col] = ph1;
            *(uint32_t*)&Ol[(size_t)rr1 * ldc + col] = pl1;
        }
    }
}

// ---------------- pad feature cols: col 512 = 1, cols 513..575 = 0 ----------------
__global__ void padfill_kernel() {
    size_t p = blockIdx.x;
    int t = threadIdx.x;     // 64
    g_fh[p * FW + HID + t] = (t == 0) ? __float2bfloat16(1.0f) : __float2bfloat16(0.0f);
    g_fl[p * FW + HID + t] = __float2bfloat16(0.0f);
}

// ---------------- transpose context features: FT[b][r][n] = F[b*NC+n][r] ----------------
__global__ void ftrans_kernel() {
    __shared__ __nv_bfloat16 th[32][33];
    __shared__ __nv_bfloat16 tl[32][33];
    int bx = blockIdx.x;   // r-tile 0..17
    int by = blockIdx.y;   // n-tile 0..31
    int b  = blockIdx.z;   // batch
    int tx = threadIdx.x;  // 0..31
    int ty = threadIdx.y;  // 0..7
    #pragma unroll
    for (int i = 0; i < 4; i++) {
        int n = by * 32 + ty + i * 8;
        int r = bx * 32 + tx;
        size_t src = ((size_t)(b * NC + n)) * FW + r;
        th[ty + i * 8][tx] = g_fh[src];
        tl[ty + i * 8][tx] = g_fl[src];
    }
    __syncthreads();
    #pragma unroll
    for (int i = 0; i < 4; i++) {
        int r = bx * 32 + ty + i * 8;
        int n = by * 32 + tx;
        size_t dst = ((size_t)b * FW + r) * NC + n;
        g_fhT[dst] = th[tx][ty + i * 8];
        g_flT[dst] = tl[tx][ty + i * 8];
    }
}

// ---------------- tensor-core SYRK: cov[b] lower tiles = F_b^T F_b ----------------
// A = FT rows [ti*64, +64), B = FT rows [tj*64, +64), K = NC = 1024.
// 8 warps (2m x 4n), warp tile 32x16. smem row stride 80B -> conflict-free ldmatrix.
#define SY_TROW  80
#define SY_TILE  (64 * SY_TROW)     // 5120
#define SY_STAGE (4 * SY_TILE)      // 20480

__global__ __launch_bounds__(256, 1)
void syrk_mma() {
    extern __shared__ __align__(1024) char smem[];
    const uint32_t sb = s2u32(smem);
    int p = blockIdx.x;        // 0..44 lower-tri pair
    int batch = blockIdx.y;
    int ti = 0;
    while ((ti + 1) * (ti + 2) / 2 <= p) ti++;
    int tj = p - ti * (ti + 1) / 2;

    const __nv_bfloat16* Th = g_fhT + (size_t)batch * FW * NC;
    const __nv_bfloat16* Tl = g_flT + (size_t)batch * FW * NC;

    const int tid = threadIdx.x;
    const int lane = tid & 31, w = tid >> 5;
    const int wm = w & 1, wn = w >> 1;

    // cp.async mapping: q = which tile (Ah,Al,Bh,Bl), r = row within tile
    const int q = tid >> 6;
    const int r = tid & 63;
    const __nv_bfloat16* srow;
    {
        int trow = (q < 2) ? (ti * 64 + r) : (tj * 64 + r);
        srow = ((q & 1) ? Tl : Th) + (size_t)trow * NC;
    }
    const uint32_t sdst = (uint32_t)q * SY_TILE + (uint32_t)r * SY_TROW;

#define SY_ISSUE(s, kc) do {                                            \
        uint32_t _b = sb + (uint32_t)(s) * SY_STAGE + sdst;             \
        const __nv_bfloat16* _g = srow + (size_t)(kc) * 32;             \
        CP16(_b,      _g);      CP16(_b + 16, _g + 8);                  \
        CP16(_b + 32, _g + 16); CP16(_b + 48, _g + 24);                 \
        CP_COMMIT();                                                    \
    } while (0)

    float acc[2][2][4];
    #pragma unroll
    for (int i = 0; i < 2; i++)
        #pragma unroll
        for (int j = 0; j < 2; j++)
            #pragma unroll
            for (int k2 = 0; k2 < 4; k2++) acc[i][j][k2] = 0.0f;

    const int rA  = ((lane >> 3) & 1) * 8 + (lane & 7);
    const int cAh = lane >> 4;
    const int idxb = lane & 15;
    const int rB  = idxb & 7;
    const int cBh = (idxb >> 3) & 1;

    SY_ISSUE(0, 0);
    SY_ISSUE(1, 1);

    for (int t = 0; t < 32; ++t) {
        if (t == 31) { CP_WAIT0(); } else { CP_WAIT1(); }
        __syncthreads();
        if (t + 2 < 32) SY_ISSUE((t + 2) % 3, t + 2);
        uint32_t base = sb + (uint32_t)(t % 3) * SY_STAGE;
        #pragma unroll
        for (int ks = 0; ks < 2; ++ks) {
            uint32_t ahf[2][4], alf[2][4], bhf[2][2], blf[2][2];
            #pragma unroll
            for (int mt = 0; mt < 2; ++mt) {
                int rowA = wm * 32 + mt * 16 + rA;
                uint32_t ad = base + (uint32_t)(rowA * SY_TROW + (ks * 2 + cAh) * 16);
                ldsm4(ahf[mt], ad);
                ldsm4(alf[mt], ad + SY_TILE);
            }
            #pragma unroll
            for (int nt = 0; nt < 2; ++nt) {
                int rowB = wn * 16 + nt * 8 + rB;
                uint32_t bd = base + 2u * SY_TILE +
                              (uint32_t)(rowB * SY_TROW + (ks * 2 + cBh) * 16);
                ldsm2(bhf[nt], bd);
                ldsm2(blf[nt], bd + SY_TILE);
            }
            #pragma unroll
            for (int mt = 0; mt < 2; ++mt)
                #pragma unroll
                for (int nt = 0; nt < 2; ++nt) {
                    mma16816(acc[mt][nt], ahf[mt], bhf[nt]);
                    mma16816(acc[mt][nt], ahf[mt], blf[nt]);
                    mma16816(acc[mt][nt], alf[mt], bhf[nt]);
                }
        }
    }
#undef SY_ISSUE

    float* Cb = g_cov + (size_t)batch * NP * NP;
    const int rbase = ti * 64 + wm * 32 + (lane >> 2);
    const int cbase = tj * 64 + wn * 16 + 2 * (lane & 3);
    #pragma unroll
    for (int nt = 0; nt < 2; ++nt) {
        int col = cbase + nt * 8;
        #pragma unroll
        for (int mt = 0; mt < 2; ++mt) {
            int rr0 = rbase + mt * 16;
            int rr1 = rr0 + 8;
            *(float2*)&Cb[(size_t)rr0 * NP + col] = make_float2(acc[mt][nt][0], acc[mt][nt][1]);
            *(float2*)&Cb[(size_t)rr1 * NP + col] = make_float2(acc[mt][nt][2], acc[mt][nt][3]);
        }
    }
}

// ---------------- xty[b] = F_b^T yc (reads transposed features) ----------------
__global__ void xty_kernel(const float* __restrict__ y) {
    int b = blockIdx.x;
    int rc = blockIdx.y;          // 0..8
    int tid = threadIdx.x;        // 256
    float2 st = g_stats[b];
    float mean = st.x, inv = 1.0f / st.y;
    __shared__ float ycs[NC];
    for (int t = tid; t < NC; t += 256) ycs[t] = (y[b * NC + t] - mean) * inv;
    __syncthreads();
    int w = tid >> 5, lane = tid & 31;
    const __nv_bfloat16* Th = g_fhT + (size_t)b * FW * NC;
    const __nv_bfloat16* Tl = g_flT + (size_t)b * FW * NC;
    for (int rr = 0; rr < 8; rr++) {
        int i = rc * 64 + w * 8 + rr;
        const __nv_bfloat16* hr = Th + (size_t)i * NC;
        const __nv_bfloat16* lr = Tl + (size_t)i * NC;
        float s = 0.0f;
        #pragma unroll 4
        for (int j = 0; j < 16; j++) {
            int n = (j * 32 + lane) * 2;
            __nv_bfloat162 hv = *(const __nv_bfloat162*)&hr[n];
            __nv_bfloat162 lv = *(const __nv_bfloat162*)&lr[n];
            float2 hf = __bfloat1622float2(hv);
            float2 lf = __bfloat1622float2(lv);
            s += (hf.x + lf.x) * ycs[n] + (hf.y + lf.y) * ycs[n + 1];
        }
        s = warpsum(s);
        if (lane == 0) g_xty[b * NP + i] = s;
    }
}

// ---------------- noise on diag + identity padding ----------------
__global__ void fix_cov_kernel(const float* __restrict__ lnv) {
    int b = blockIdx.x, i = threadIdx.x;   // 576
    float noise = expf(lnv[0]);
    float* d = g_cov + (size_t)b * NP * NP + (size_t)i * NP + i;
    if (i < 513) *d += noise; else *d = 1.0f;
}

// ---------------- Cholesky: diagonal block factor ----------------
__global__ void chol_diag_kernel(int k) {
    __shared__ float D[64][65];
    float* Cb = g_cov + (size_t)blockIdx.x * NP * NP;
    int tid = threadIdx.x;   // 256
    for (int idx = tid; idx < 4096; idx += 256) {
        int i = idx >> 6, j = idx & 63;
        D[i][j] = Cb[(size_t)(k * 64 + i) * NP + k * 64 + j];
    }
    __syncthreads();
    for (int c = 0; c < 64; c++) {
        if (tid == 0) D[c][c] = sqrtf(D[c][c]);
        __syncthreads();
        float dc = D[c][c];
        if (tid > c && tid < 64) D[tid][c] /= dc;
        __syncthreads();
        for (int idx = tid; idx < 4096; idx += 256) {
            int i = idx >> 6, j = idx & 63;
            if (j > c && j <= i) D[i][j] -= D[i][c] * D[j][c];
        }
        __syncthreads();
    }
    for (int idx = tid; idx < 4096; idx += 256) {
        int i = idx >> 6, j = idx & 63;
        Cb[(size_t)(k * 64 + i) * NP + k * 64 + j] = (j <= i) ? D[i][j] : 0.0f;
    }
}

// ---------------- Cholesky: panel triangular solve ----------------
__global__ void chol_panel_kernel(int k, int ntiles) {
    int bx = blockIdx.x;
    int batch = bx / ntiles;
    int ib = k + 1 + (bx % ntiles);
    float* Cb = g_cov + (size_t)batch * NP * NP;
    __shared__ float D[64][65];
    __shared__ float X[64][65];
    int tid = threadIdx.x;   // 128
    for (int idx = tid; idx < 4096; idx += 128) {
        int i = idx >> 6, j = idx & 63;
        D[i][j] = Cb[(size_t)(k * 64 + i) * NP + k * 64 + j];
        X[i][j] = Cb[(size_t)(ib * 64 + i) * NP + k * 64 + j];
    }
    __syncthreads();
    if (tid < 64) {
        int r = tid;
        for (int c = 0; c < 64; c++) {
            float s = X[r][c];
            for (int j = 0; j < c; j++) s -= X[r][j] * D[c][j];
            X[r][c] = s / D[c][c];
        }
    }
    __syncthreads();
    for (int idx = tid; idx < 4096; idx += 128) {
        int i = idx >> 6, j = idx & 63;
        Cb[(size_t)(ib * 64 + i) * NP + k * 64 + j] = X[i][j];
    }
}

// ---------------- Cholesky: trailing update ----------------
__global__ __launch_bounds__(256)
void chol_update_kernel(int k, int npairs) {
    int bx = blockIdx.x;
    int batch = bx / npairs;
    int p = bx % npairs;
    int a = 0;
    while ((a + 1) * (a + 2) / 2 <= p) a++;
    int b2 = p - a * (a + 1) / 2;
    int ib = k + 1 + a, jb = k + 1 + b2;
    float* Cb = g_cov + (size_t)batch * NP * NP;

    __shared__ __align__(16) float LiT[64][68];
    __shared__ __align__(16) float LjT[64][68];
    int tid = threadIdx.x;
    for (int idx = tid; idx < 1024; idx += 256) {
        int r2 = idx >> 4;
        int c4 = (idx & 15) * 4;
        float4 v = *(const float4*)&Cb[(size_t)(ib * 64 + r2) * NP + k * 64 + c4];
        LiT[c4 + 0][r2] = v.x; LiT[c4 + 1][r2] = v.y; LiT[c4 + 2][r2] = v.z; LiT[c4 + 3][r2] = v.w;
        float4 u = *(const float4*)&Cb[(size_t)(jb * 64 + r2) * NP + k * 64 + c4];
        LjT[c4 + 0][r2] = u.x; LjT[c4 + 1][r2] = u.y; LjT[c4 + 2][r2] = u.z; LjT[c4 + 3][r2] = u.w;
    }
    __syncthreads();

    int ty = tid >> 4, tx = tid & 15;
    float acc[4][4];
    #pragma unroll
    for (int i = 0; i < 4; i++)
        #pragma unroll
        for (int j = 0; j < 4; j++) acc[i][j] = 0.0f;

    #pragma unroll 4
    for (int c = 0; c < 64; c++) {
        float4 av = *(const float4*)&LiT[c][ty * 4];
        float4 bv = *(const float4*)&LjT[c][tx * 4];
        float a_[4] = { av.x, av.y, av.z, av.w };
        float b_[4] = { bv.x, bv.y, bv.z, bv.w };
        #pragma unroll
        for (int i = 0; i < 4; i++)
            #pragma unroll
            for (int j = 0; j < 4; j++)
                acc[i][j] += a_[i] * b_[j];
    }

    #pragma unroll
    for (int i = 0; i < 4; i++) {
        int gi = ib * 64 + ty * 4 + i;
        float4* cp = (float4*)&Cb[(size_t)gi * NP + jb * 64 + tx * 4];
        float4 old = *cp;
        *cp = make_float4(old.x - acc[i][0], old.y - acc[i][1],
                          old.z - acc[i][2], old.w - acc[i][3]);
    }
}

// ---------------- triangular solves: L z = xty; L^T w = z ----------------
__global__ void solve_kernel() {
    int b = blockIdx.x, tid = threadIdx.x;  // 256
    const float* L = g_cov + (size_t)b * NP * NP;
    __shared__ float z[NP];
    for (int t = tid; t < NP; t += 256) z[t] = g_xty[b * NP + t];
    __syncthreads();
    int warp = tid >> 5, lane = tid & 31;

    for (int kb = 0; kb < NBLK; kb++) {
        int i0 = kb * 64;
        if (kb > 0) {
            for (int r = warp; r < 64; r += 8) {
                const float* Lr = L + (size_t)(i0 + r) * NP;
                float s = 0.0f;
                for (int j = lane; j < i0; j += 32) s += Lr[j] * z[j];
                s = warpsum(s);
                if (lane == 0) z[i0 + r] -= s;
            }
        }
        __syncthreads();
        if (warp == 0) {
            for (int c = 0; c < 64; c++) {
                int i = i0 + c;
                float zc = 0.0f;
                if (lane == 0) { zc = z[i] / L[(size_t)i * NP + i]; z[i] = zc; }
                zc = __shfl_sync(0xffffffffu, zc, 0);
                for (int r = c + 1 + lane; r < 64; r += 32)
                    z[i0 + r] -= L[(size_t)(i0 + r) * NP + i] * zc;
                __syncwarp();
            }
        }
        __syncthreads();
    }

    for (int kb = NBLK - 1; kb >= 0; kb--) {
        int i0 = kb * 64;
        if (kb < NBLK - 1) {
            for (int r = warp; r < 64; r += 8) {
                int i = i0 + r;
                float s = 0.0f;
                for (int j = i0 + 64 + lane; j < NP; j += 32)
                    s += L[(size_t)j * NP + i] * z[j];
                s = warpsum(s);
                if (lane == 0) z[i] -= s;
            }
        }
        __syncthreads();
        if (warp == 0) {
            for (int c = 63; c >= 0; c--) {
                int i = i0 + c;
                float zc = 0.0f;
                if (lane == 0) { zc = z[i] / L[(size_t)i * NP + i]; z[i] = zc; }
                zc = __shfl_sync(0xffffffffu, zc, 0);
                for (int r = lane; r < c; r += 32)
                    z[i0 + r] -= L[(size_t)i * NP + i0 + r] * zc;
                __syncwarp();
            }
        }
        __syncthreads();
    }
    for (int t = tid; t < NP; t += 256) g_w[b * NP + t] = z[t];
}

// ---------------- prediction: y = (tr . w) * std + mean ----------------
__global__ void predict_kernel(float* __restrict__ out) {
    int b = blockIdx.x, chunk = blockIdx.y;
    __shared__ float ws[NP];
    int tid = threadIdx.x;  // 256
    for (int t = tid; t < NP; t += 256) ws[t] = g_w[b * NP + t];
    __syncthreads();
    float2 st = g_stats[b];
    int warp = tid >> 5, lane = tid & 31;
    for (int r = warp; r < 64; r += 8) {
        int m = chunk * 64 + r;
        size_t row = (size_t)(BATCH * NC + b * NT + m) * FW;
        const __nv_bfloat16* hr = g_fh + row;
        const __nv_bfloat16* lr = g_fl + row;
        float s = 0.0f;
        #pragma unroll
        for (int it = 0; it < 9; it++) {
            int j = it * 64 + lane * 2;
            __nv_bfloat162 hv = *(const __nv_bfloat162*)&hr[j];
            __nv_bfloat162 lv = *(const __nv_bfloat162*)&lr[j];
            float2 hf = __bfloat1622float2(hv);
            float2 lf = __bfloat1622float2(lv);
            s += (hf.x + lf.x) * ws[j] + (hf.y + lf.y) * ws[j + 1];
        }
        s = warpsum(s);
        if (lane == 0) out[b * NT + m] = s * st.y + st.x;
    }
}

// ---------------- launcher ----------------
extern "C" void kernel_launch(void* const* d_in, const int* in_sizes, int n_in,
                              void* d_out, int out_size) {
    const float* xc  = (const float*)d_in[0];
    const float* yc  = (const float*)d_in[1];
    const float* xt  = (const float*)d_in[2];
    const float* W0  = (const float*)d_in[3];
    const float* b0  = (const float*)d_in[4];
    const float* W1  = (const float*)d_in[5];
    const float* b1  = (const float*)d_in[6];
    const float* W2  = (const float*)d_in[7];
    const float* b2  = (const float*)d_in[8];
    const float* Wr  = (const float*)d_in[9];
    const float* br  = (const float*)d_in[10];
    const float* lnv = (const float*)d_in[11];
    float* out = (float*)d_out;

    cudaFuncSetAttribute(mma_gemm, cudaFuncAttributeMaxDynamicSharedMemorySize,
                         3 * MMG_STAGE);
    cudaFuncSetAttribute(syrk_mma, cudaFuncAttributeMaxDynamicSharedMemorySize,
                         3 * SY_STAGE);

    stats_kernel<<<BATCH, 256>>>(yc);
    wsplit_kernel<<<dim3(HID, 3), HID>>>(W1, W2, Wr);
    layer0_kernel<<<PTS, 128>>>(xc, xt, W0, b0);

    dim3 gg(4, PTS / 128);   // x = N-blocks (fast) so A tiles are reused in L2
    mma_gemm<<<gg, 256, 3 * MMG_STAGE>>>(0, 0, b1, 0, HID, 1);  // -> (h1,l1), sin
    mma_gemm<<<gg, 256, 3 * MMG_STAGE>>>(1, 1, b2, 1, HID, 1);  // -> (h0,l0), sin
    mma_gemm<<<gg, 256, 3 * MMG_STAGE>>>(0, 2, br, 2, FW, 0);   // -> (fh,fl), no sin

    padfill_kernel<<<PTS, 64>>>();
    ftrans_kernel<<<dim3(18, 32, BATCH), dim3(32, 8)>>>();

    syrk_mma<<<dim3(45, BATCH), 256, 3 * SY_STAGE>>>();
    xty_kernel<<<dim3(BATCH, 9), 256>>>(yc);
    fix_cov_kernel<<<BATCH, NP>>>(lnv);

    for (int k = 0; k < NBLK; k++) {
        chol_diag_kernel<<<BATCH, 256>>>(k);
        int T = NBLK - 1 - k;
        if (T > 0) {
            chol_panel_kernel<<<BATCH * T, 128>>>(k, T);
            int np = T * (T + 1) / 2;
            chol_update_kernel<<<BATCH * np, 256>>>(k, np);
        }
    }

    solve_kernel<<<BATCH, 256>>>();
    predict_kernel<<<dim3(BATCH, NT / 64), 256>>>(out);
}